// round 4
// baseline (speedup 1.0000x reference)
#include <cuda_runtime.h>
#include <cuda_bf16.h>

// DensityEstimator: per-channel 1->3->3->3->1 MLP, p = cdf(x+.5) - cdf(x-.5)
// R4: latency-bound fix -- 2 elements per thread per iteration (4 independent
// p/m activation chains interleaved) to cover MUFU latency. Grid 384x256:
// T = 98304 = 192*512 (channel-invariant), n/(2T) = 64 exact iterations,
// one wave at 3 blocks/SM (85-reg budget).

#define NCH 192
#define NBLK 384
#define NTHR 256

__device__ __forceinline__ float tanha(float x) {
    float r; asm("tanh.approx.f32 %0, %1;" : "=f"(r) : "f"(x)); return r;
}

// Accurate softplus for the one-time weight transform.
__device__ __forceinline__ float softplus_acc(float h) {
    return (h > 15.0f) ? h : log1pf(expf(h));
}

struct W {
    float sh0[3], sh1[9], sh2[9], sh3[3];
    float ta0[3], ta1[3], ta2[3];
    float bp0[3], bm0[3], bb1[3], bb2[3], bb3;
};

// One element: full dual (p/m) MLP chain -> 0.5*(tanh(fp/2)-tanh(fm/2)).
// Inlined twice per iteration; ptxas interleaves the independent chains.
__device__ __forceinline__ float de_one(float xv, const W& w) {
    float yp[3], ym[3];
#pragma unroll
    for (int j = 0; j < 3; j++) {
        float tp = fmaf(xv, w.sh0[j], w.bp0[j]);
        float tm = fmaf(xv, w.sh0[j], w.bm0[j]);
        yp[j] = fmaf(w.ta0[j], tanha(tp), tp);
        ym[j] = fmaf(w.ta0[j], tanha(tm), tm);
    }
    float zp[3], zm[3];
#pragma unroll
    for (int p = 0; p < 3; p++) {
        float sp = w.bb1[p], sm = w.bb1[p];
#pragma unroll
        for (int j = 0; j < 3; j++) {
            sp = fmaf(yp[j], w.sh1[j*3 + p], sp);
            sm = fmaf(ym[j], w.sh1[j*3 + p], sm);
        }
        zp[p] = fmaf(w.ta1[p], tanha(sp), sp);
        zm[p] = fmaf(w.ta1[p], tanha(sm), sm);
    }
#pragma unroll
    for (int p = 0; p < 3; p++) {
        float sp = w.bb2[p], sm = w.bb2[p];
#pragma unroll
        for (int j = 0; j < 3; j++) {
            sp = fmaf(zp[j], w.sh2[j*3 + p], sp);
            sm = fmaf(zm[j], w.sh2[j*3 + p], sm);
        }
        yp[p] = fmaf(w.ta2[p], tanha(sp), sp);
        ym[p] = fmaf(w.ta2[p], tanha(sm), sm);
    }
    float fp = w.bb3, fm = w.bb3;
#pragma unroll
    for (int j = 0; j < 3; j++) {
        fp = fmaf(yp[j], w.sh3[j], fp);
        fm = fmaf(ym[j], w.sh3[j], fm);
    }
    return 0.5f * (tanha(fp) - tanha(fm));
}

__global__ void __launch_bounds__(NTHR, 3) de_kernel(
    const float* __restrict__ x,
    const float* __restrict__ a0, const float* __restrict__ a1, const float* __restrict__ a2,
    const float* __restrict__ b0, const float* __restrict__ b1, const float* __restrict__ b2,
    const float* __restrict__ b3,
    const float* __restrict__ H0, const float* __restrict__ H1, const float* __restrict__ H2,
    const float* __restrict__ H3,
    float* __restrict__ out, int n)
{
    const int T  = gridDim.x * blockDim.x;          // 98304, multiple of 192
    const int i0 = blockIdx.x * blockDim.x + threadIdx.x;
    const int c  = i0 % NCH;                        // fixed channel (T % 192 == 0)

    // One-time per-thread weight transform into registers.
    W w;
#pragma unroll
    for (int j = 0; j < 3; j++) {
        w.sh0[j] = softplus_acc(__ldg(&H0[c*3 + j]));          // H0: (C,1,3)
        w.sh3[j] = 0.5f * softplus_acc(__ldg(&H3[c*3 + j]));   // H3: (C,3,1), 1/2 folded
        w.ta0[j] = tanhf(__ldg(&a0[c*3 + j]));
        w.ta1[j] = tanhf(__ldg(&a1[c*3 + j]));
        w.ta2[j] = tanhf(__ldg(&a2[c*3 + j]));
        float b0j = __ldg(&b0[c*3 + j]);
        w.bp0[j] = fmaf( 0.5f, w.sh0[j], b0j);                 // fold x+0.5 into bias
        w.bm0[j] = fmaf(-0.5f, w.sh0[j], b0j);                 // fold x-0.5 into bias
        w.bb1[j] = __ldg(&b1[c*3 + j]);
        w.bb2[j] = __ldg(&b2[c*3 + j]);
    }
#pragma unroll
    for (int j = 0; j < 9; j++) {
        w.sh1[j] = softplus_acc(__ldg(&H1[c*9 + j]));          // H1: (C,3,3) [i*3+p]
        w.sh2[j] = softplus_acc(__ldg(&H2[c*9 + j]));
    }
    w.bb3 = 0.5f * __ldg(&b3[c]);                              // 1/2 folded

    // Two elements per iteration: i and i+T share the same channel.
    for (int i = i0; i < n; i += 2 * T) {
        int  i2  = i + T;
        bool ok2 = i2 < n;
        float xa = x[i];
        float xb = x[ok2 ? i2 : i];
        float ra = de_one(xa, w);
        float rb = de_one(xb, w);
        out[i] = ra;
        if (ok2) out[i2] = rb;
    }
}

extern "C" void kernel_launch(void* const* d_in, const int* in_sizes, int n_in,
                              void* d_out, int out_size)
{
    const float* x  = (const float*)d_in[0];
    const float* a0 = (const float*)d_in[1];
    const float* a1 = (const float*)d_in[2];
    const float* a2 = (const float*)d_in[3];
    const float* b0 = (const float*)d_in[4];
    const float* b1 = (const float*)d_in[5];
    const float* b2 = (const float*)d_in[6];
    const float* b3 = (const float*)d_in[7];
    const float* H0 = (const float*)d_in[8];
    const float* H1 = (const float*)d_in[9];
    const float* H2 = (const float*)d_in[10];
    const float* H3 = (const float*)d_in[11];
    float* out = (float*)d_out;
    int n = in_sizes[0];   // 65536 * 192

    de_kernel<<<NBLK, NTHR>>>(x, a0, a1, a2, b0, b1, b2, b3,
                              H0, H1, H2, H3, out, n);
}